// round 4
// baseline (speedup 1.0000x reference)
#include <cuda_runtime.h>
#include <cstdint>
#include <cstddef>

// GRU scan, T=1024, rows = B*A = 128, H = 256.
// 16 clusters x 8 CTAs. Cluster owns 8 rows; CTA owns 32 output columns of all
// six weight matrices, resident in shared memory for the whole scan.
// Split cluster barrier per timestep (arrive after DSMEM broadcast, wait just
// before consuming peers' writes); new-h slices exchanged via DSMEM.

#define NT   1024
#define NR   128          // B*A rows
#define NH   256          // hidden
#define CSIZE 8           // cluster size (CTAs per cluster)
#define RPC  8            // rows per cluster
#define CPC  32           // columns per CTA
#define WPAD 260          // padded k-stride for conflict-free float4 LDS
#define MATS (CPC*WPAD)   // floats per weight matrix slice = 8320

#define SMEM_FLOATS (6*MATS + 2*RPC*NH + RPC*NH + RPC*CPC + 4*CPC)
#define SMEM_BYTES  (SMEM_FLOATS*4)

__device__ __forceinline__ float fsig(float x)  { return 1.0f/(1.0f + __expf(-x)); }
__device__ __forceinline__ float ftanh(float x) { return 1.0f - 2.0f/(__expf(2.0f*x) + 1.0f); }

#define DOT4(acc,u,v) acc = fmaf((u).x,(v).x, fmaf((u).y,(v).y, fmaf((u).z,(v).z, fmaf((u).w,(v).w,(acc)))))

#define CLUSTER_ARRIVE() asm volatile("barrier.cluster.arrive.aligned;" ::: "memory")
#define CLUSTER_WAIT()   asm volatile("barrier.cluster.wait.aligned;"   ::: "memory")

extern __shared__ float smem[];

__global__ void __launch_bounds__(128, 1) __cluster_dims__(CSIZE, 1, 1)
gru_scan(const float* __restrict__ ins, const int* __restrict__ resets,
         const float* __restrict__ h0,
         const float* __restrict__ Wir, const float* __restrict__ Wiz, const float* __restrict__ Win,
         const float* __restrict__ bir, const float* __restrict__ biz, const float* __restrict__ bin,
         const float* __restrict__ Whr, const float* __restrict__ Whz, const float* __restrict__ Whn,
         const float* __restrict__ bhn,
         float* __restrict__ out)
{
    float* Ws  = smem;                 // [6][CPC][WPAD]  weights, [j][k] layout
    float* hb  = Ws + 6*MATS;          // [2][RPC][NH]    h double buffer (full rows)
    float* xs  = hb + 2*RPC*NH;        // [RPC][NH]       current ins slice
    float* stg = xs + RPC*NH;          // [RPC][CPC]      my new-h slice staging
    float* bsm = stg + RPC*CPC;        // [4][CPC]        b_ir, b_iz, b_in, b_hn slices

    const int tid   = threadIdx.x;
    const int jj    = tid & 31;        // local column
    const int rg    = tid >> 5;        // row group (2 rows each)
    const int rank  = blockIdx.x & (CSIZE-1);
    const int rbase = (blockIdx.x / CSIZE) * RPC;
    const int jbase = rank * CPC;

    // ---- load weight slices (transpose [k][j] -> [j][k], coalesced gmem reads)
    {
        const float* srcs[6] = {Wir, Wiz, Win, Whr, Whz, Whn};
        #pragma unroll
        for (int m = 0; m < 6; m++) {
            const float* Wm = srcs[m];
            float* Wd = Ws + m*MATS + jj*WPAD;
            for (int k0 = 0; k0 < NH; k0 += 4) {
                int k = k0 + rg;
                Wd[k] = Wm[(size_t)k*NH + jbase + jj];
            }
        }
    }
    if (tid < CPC) {
        bsm[tid]         = bir[jbase + tid];
        bsm[CPC + tid]   = biz[jbase + tid];
        bsm[2*CPC + tid] = bin[jbase + tid];
        bsm[3*CPC + tid] = bhn[jbase + tid];
    }
    // ---- h0 into buffer 0 (full 8 rows x 256)
    {
        const float4* s = (const float4*)(h0 + (size_t)rbase*NH);
        float4* d = (float4*)hb;
        for (int i = tid; i < RPC*NH/4; i += 128) d[i] = s[i];
    }
    // ---- prefetch ins for t=0 into registers
    float4 px0, px1, px2, px3;
    {
        const float4* s = (const float4*)(ins + (size_t)rbase*NH);
        px0 = s[tid*4+0]; px1 = s[tid*4+1]; px2 = s[tid*4+2]; px3 = s[tid*4+3];
    }

    CLUSTER_ARRIVE();   // pairs with the CLUSTER_WAIT at the top of iteration 0

    const float c_bir = bsm[jj], c_biz = bsm[CPC+jj], c_bin = bsm[2*CPC+jj], c_bhn = bsm[3*CPC+jj];
    const int r0 = rg*2, r1 = r0 + 1;
    const uint32_t hb_s = (uint32_t)__cvta_generic_to_shared(hb);

    for (int t = 0; t < NT; t++) {
        const int p = t & 1;
        float* hcur = hb + p*(RPC*NH);

        // CTA-private work first: stage prefetched x into smem, prefetch next x.
        // This overlaps with peers reaching their barrier arrive.
        {
            float4* d = (float4*)xs;
            d[tid*4+0] = px0; d[tid*4+1] = px1; d[tid*4+2] = px2; d[tid*4+3] = px3;
        }
        if (t + 1 < NT) {
            const float4* s = (const float4*)(ins + ((size_t)(t+1)*NR + rbase)*NH);
            px0 = s[tid*4+0]; px1 = s[tid*4+1]; px2 = s[tid*4+2]; px3 = s[tid*4+3];
        }

        // Acquire peers' DSMEM writes into hcur (and, for t>0, confirm peers
        // finished reading the buffer we are about to overwrite this step).
        CLUSTER_WAIT();

        // reset masking: zero my local copy of h rows that reset this step
        {
            int row = tid >> 4;   // each row handled by 16 threads
            if (resets[(size_t)t*NR + rbase + row] != 0) {
                float4* d = (float4*)(hcur + row*NH) + (tid & 15)*4;
                float4 z = make_float4(0.f, 0.f, 0.f, 0.f);
                d[0] = z; d[1] = z; d[2] = z; d[3] = z;
            }
        }
        __syncthreads();

        // ---- six matvecs (2 rows x 1 col per thread, x/h broadcast within warp)
        float a0=0,a1=0,a2=0,a3=0,a4=0,a5=0;   // row r0: xWir,xWiz,xWin,hWhr,hWhz,hWhn
        float q0=0,q1=0,q2=0,q3=0,q4=0,q5=0;   // row r1
        const float* wbase = Ws + jj*WPAD;
        const float* x0p = xs + r0*NH;
        const float* x1p = xs + r1*NH;
        const float* h0p = hcur + r0*NH;
        const float* h1p = hcur + r1*NH;
        #pragma unroll 4
        for (int k = 0; k < NH; k += 4) {
            float4 xv0 = *(const float4*)(x0p + k);
            float4 xv1 = *(const float4*)(x1p + k);
            float4 hv0 = *(const float4*)(h0p + k);
            float4 hv1 = *(const float4*)(h1p + k);
            float4 w;
            w = *(const float4*)(wbase + 0*MATS + k); DOT4(a0,xv0,w); DOT4(q0,xv1,w);
            w = *(const float4*)(wbase + 1*MATS + k); DOT4(a1,xv0,w); DOT4(q1,xv1,w);
            w = *(const float4*)(wbase + 2*MATS + k); DOT4(a2,xv0,w); DOT4(q2,xv1,w);
            w = *(const float4*)(wbase + 3*MATS + k); DOT4(a3,hv0,w); DOT4(q3,hv1,w);
            w = *(const float4*)(wbase + 4*MATS + k); DOT4(a4,hv0,w); DOT4(q4,hv1,w);
            w = *(const float4*)(wbase + 5*MATS + k); DOT4(a5,hv0,w); DOT4(q5,hv1,w);
        }

        // ---- gates
        float hold0 = hcur[r0*NH + jbase + jj];
        float hold1 = hcur[r1*NH + jbase + jj];
        float rr0 = fsig(a0 + c_bir + a3);
        float zz0 = fsig(a1 + c_biz + a4);
        float nn0 = ftanh(a2 + c_bin + rr0*(a5 + c_bhn));
        float hn0 = (1.0f - zz0)*nn0 + zz0*hold0;
        float rr1 = fsig(q0 + c_bir + q3);
        float zz1 = fsig(q1 + c_biz + q4);
        float nn1 = ftanh(q2 + c_bin + rr1*(q5 + c_bhn));
        float hn1 = (1.0f - zz1)*nn1 + zz1*hold1;

        // ---- write output ys[t, rows, my cols] (coalesced 128B per warp)
        float* ob = out + ((size_t)t*NR + rbase)*NH + jbase + jj;
        ob[r0*NH] = hn0;
        ob[r1*NH] = hn1;

        // ---- stage my slice, then broadcast to all 8 cluster CTAs' next buffer
        stg[r0*CPC + jj] = hn0;
        stg[r1*CPC + jj] = hn1;
        __syncthreads();
        {
            const uint32_t hn_off = hb_s + (uint32_t)((1-p)*(RPC*NH))*4u;
            #pragma unroll
            for (int w = 0; w < 4; w++) {
                int c   = tid + w*128;      // 0..511 over (rank, row, col4)
                int rk  = c >> 6;
                int f4  = c & 63;
                int row = f4 >> 3;
                int c4  = f4 & 7;
                float4 v = *(const float4*)(stg + row*CPC + c4*4);
                uint32_t laddr = hn_off + (uint32_t)(row*NH + jbase + c4*4)*4u;
                uint32_t raddr;
                asm("mapa.shared::cluster.u32 %0, %1, %2;" : "=r"(raddr) : "r"(laddr), "r"(rk));
                asm volatile("st.shared::cluster.v4.f32 [%0], {%1,%2,%3,%4};"
                             :: "r"(raddr), "f"(v.x), "f"(v.y), "f"(v.z), "f"(v.w) : "memory");
            }
        }
        CLUSTER_ARRIVE();   // release DSMEM writes; matching wait at top of t+1
    }
}

extern "C" void kernel_launch(void* const* d_in, const int* in_sizes, int n_in,
                              void* d_out, int out_size)
{
    const float* ins    = (const float*)d_in[0];
    const int*   resets = (const int*)d_in[1];     // jax bool -> int32 in harness
    const float* h0     = (const float*)d_in[2];
    const float* Wir    = (const float*)d_in[3];
    const float* Wiz    = (const float*)d_in[4];
    const float* Win    = (const float*)d_in[5];
    const float* bir    = (const float*)d_in[6];
    const float* biz    = (const float*)d_in[7];
    const float* bin    = (const float*)d_in[8];
    const float* Whr    = (const float*)d_in[9];
    const float* Whz    = (const float*)d_in[10];
    const float* Whn    = (const float*)d_in[11];
    const float* bhn    = (const float*)d_in[12];
    float* out = (float*)d_out;

    cudaFuncSetAttribute(gru_scan, cudaFuncAttributeMaxDynamicSharedMemorySize, SMEM_BYTES);
    gru_scan<<<NR, 128, SMEM_BYTES>>>(ins, resets, h0,
                                      Wir, Wiz, Win, bir, biz, bin,
                                      Whr, Whz, Whn, bhn, out);
}

// round 6
// speedup vs baseline: 1.0963x; 1.0963x over previous
#include <cuda_runtime.h>
#include <cstdint>
#include <cstddef>

// GRU scan, T=1024, rows = B*A = 128, H = 256.
// 16 clusters x 8 CTAs, 256 threads/CTA, warp-specialized:
//   warps 0-3 ("h-group"): recurrent matvecs + gates for step t (serial path)
//   warps 4-7 ("x-group"): input projections for step t+1 (no serial dep)
// f32x2 packed FMA (FFMA2) halves FFMA issue. Lane mapping 8 cols x 4 row-groups
// makes weight LDS 1-phase broadcasts. Split cluster barrier per step.

#define NT   1024
#define NR   128
#define NH   256
#define CSIZE 8
#define RPC  8            // rows per cluster
#define CPC  32           // cols per CTA
#define WPAD 260          // padded k-stride (bank-conflict-free)
#define MATS (CPC*WPAD)   // 8320 floats per weight slice
#define HSTRIDE 260       // padded row stride for h / x tiles

#define SMEM_FLOATS (6*MATS + 2*RPC*HSTRIDE + RPC*HSTRIDE + 2*3*RPC*CPC + RPC*CPC + 4*CPC)
#define SMEM_BYTES  (SMEM_FLOATS*4)   // 232320 B

#define FMA2(acc, a, b) asm("fma.rn.f32x2 %0, %1, %2, %0;" : "+l"(acc) : "l"(a), "l"(b))

__device__ __forceinline__ float tanh_fast(float x) {
    float y; asm("tanh.approx.f32 %0, %1;" : "=f"(y) : "f"(x)); return y;
}
__device__ __forceinline__ float sigf(float x) {       // exact identity: sig(x)=0.5*(1+tanh(x/2))
    return fmaf(0.5f, tanh_fast(0.5f*x), 0.5f);
}
__device__ __forceinline__ float pairsum(uint64_t v) {
    return __uint_as_float((uint32_t)v) + __uint_as_float((uint32_t)(v >> 32));
}

#define CLUSTER_ARRIVE() asm volatile("barrier.cluster.arrive.aligned;" ::: "memory")
#define CLUSTER_WAIT()   asm volatile("barrier.cluster.wait.aligned;"   ::: "memory")

extern __shared__ float smem[];

// Input projection for one CTA slice: 3 mats, 2 rows, 1 col per thread.
__device__ __forceinline__ void xproj(const float* Ws, const float* xs, float* xgbuf,
                                      int col, int r0, int r1,
                                      float c_bir, float c_biz, float c_bin)
{
    const ulonglong2* W0 = (const ulonglong2*)(Ws + 0*MATS + col*WPAD);
    const ulonglong2* W1 = (const ulonglong2*)(Ws + 1*MATS + col*WPAD);
    const ulonglong2* W2 = (const ulonglong2*)(Ws + 2*MATS + col*WPAD);
    const ulonglong2* X0 = (const ulonglong2*)(xs + r0*HSTRIDE);
    const ulonglong2* X1 = (const ulonglong2*)(xs + r1*HSTRIDE);
    uint64_t a0=0,a1=0,a2=0,a3=0,a4=0,a5=0;
    #pragma unroll 4
    for (int k4 = 0; k4 < NH/4; k4++) {
        ulonglong2 w0 = W0[k4], w1 = W1[k4], w2 = W2[k4];
        ulonglong2 x0 = X0[k4], x1 = X1[k4];
        FMA2(a0, w0.x, x0.x); FMA2(a0, w0.y, x0.y);
        FMA2(a1, w1.x, x0.x); FMA2(a1, w1.y, x0.y);
        FMA2(a2, w2.x, x0.x); FMA2(a2, w2.y, x0.y);
        FMA2(a3, w0.x, x1.x); FMA2(a3, w0.y, x1.y);
        FMA2(a4, w1.x, x1.x); FMA2(a4, w1.y, x1.y);
        FMA2(a5, w2.x, x1.x); FMA2(a5, w2.y, x1.y);
    }
    xgbuf[0*256 + r0*32 + col] = pairsum(a0) + c_bir;
    xgbuf[1*256 + r0*32 + col] = pairsum(a1) + c_biz;
    xgbuf[2*256 + r0*32 + col] = pairsum(a2) + c_bin;
    xgbuf[0*256 + r1*32 + col] = pairsum(a3) + c_bir;
    xgbuf[1*256 + r1*32 + col] = pairsum(a4) + c_biz;
    xgbuf[2*256 + r1*32 + col] = pairsum(a5) + c_bin;
}

__global__ void __launch_bounds__(256, 1) __cluster_dims__(CSIZE, 1, 1)
gru_scan(const float* __restrict__ ins, const int* __restrict__ resets,
         const float* __restrict__ h0,
         const float* __restrict__ Wir, const float* __restrict__ Wiz, const float* __restrict__ Win,
         const float* __restrict__ bir, const float* __restrict__ biz, const float* __restrict__ bin,
         const float* __restrict__ Whr, const float* __restrict__ Whz, const float* __restrict__ Whn,
         const float* __restrict__ bhn,
         float* __restrict__ out)
{
    float* Ws  = smem;                      // [6][CPC][WPAD] weights [j][k]
    float* hb  = Ws + 6*MATS;               // [2][RPC][HSTRIDE] h double buffer
    float* xs  = hb + 2*RPC*HSTRIDE;        // [RPC][HSTRIDE] ins slice (single buffer)
    float* xg  = xs + RPC*HSTRIDE;          // [2][3][RPC][CPC] x-projection double buffer
    float* stg = xg + 2*3*RPC*CPC;          // [RPC][CPC] new-h staging
    float* bsm = stg + RPC*CPC;             // [4][CPC] biases

    const int tid   = threadIdx.x;
    const int rank  = blockIdx.x & (CSIZE-1);
    const int rbase = (blockIdx.x / CSIZE) * RPC;
    const int jbase = rank * CPC;

    // ---- weights: transpose [k][j] -> [j][k]
    {
        const float* srcs[6] = {Wir, Wiz, Win, Whr, Whz, Whn};
        int jj2 = tid & 31, ks = tid >> 5;
        #pragma unroll
        for (int m = 0; m < 6; m++) {
            const float* Wm = srcs[m];
            float* Wd = Ws + m*MATS + jj2*WPAD;
            for (int k0 = 0; k0 < NH; k0 += 8) {
                int k = k0 + ks;
                Wd[k] = Wm[(size_t)k*NH + jbase + jj2];
            }
        }
    }
    if (tid < CPC) {
        bsm[tid]      = bir[jbase + tid];
        bsm[32 + tid] = biz[jbase + tid];
        bsm[64 + tid] = bin[jbase + tid];
        bsm[96 + tid] = bhn[jbase + tid];
    }
    // ---- h0 -> hb buf0 ; ins[0] -> xs  (padded row stride)
    for (int i = tid; i < RPC*NH/4; i += 256) {
        int r = i >> 6, c4 = i & 63;
        ((float4*)(hb + r*HSTRIDE))[c4] = ((const float4*)h0)[(size_t)rbase*64 + i];
        ((float4*)(xs + r*HSTRIDE))[c4] = ((const float4*)ins)[(size_t)rbase*64 + i];
    }
    __syncthreads();

    // ---- lane mapping: warp = 8 cols x 4 row-groups
    const int lane = tid & 31;
    const int colg = lane & 7, rowb = lane >> 3;
    const int r0 = rowb*2, r1 = r0 + 1;
    const bool is_h = (tid < 128);
    const int w   = (tid & 127) >> 5;
    const int col = w*8 + colg;             // 0..31 within CTA
    const float c_bir = bsm[col], c_biz = bsm[32+col], c_bin = bsm[64+col], c_bhn = bsm[96+col];

    float4 px0, px1, px2, px3;
    if (!is_h) {
        // prologue: xg[0] from ins[0]; prefetch ins[1]
        xproj(Ws, xs, xg, col, r0, r1, c_bir, c_biz, c_bin);
        int xt = tid - 128;
        const float4* s = (const float4*)ins + (size_t)(1*NR + rbase)*64;
        px0 = s[xt*4+0]; px1 = s[xt*4+1]; px2 = s[xt*4+2]; px3 = s[xt*4+3];
    }
    CLUSTER_ARRIVE();   // releases xg[0] (+h0/weights); pairs with wait at t=0

    const uint32_t hb_s = (uint32_t)__cvta_generic_to_shared(hb);

    for (int t = 0; t < NT; t++) {
        const int p = t & 1;
        float* hcur = hb + p*(RPC*HSTRIDE);

        CLUSTER_WAIT();   // acquire peers' h pushes (and xg handoff within CTA)

        if (is_h) {
            // reset masking
            {
                int row = tid >> 4;
                if (resets[(size_t)t*NR + rbase + row] != 0) {
                    float4* d = (float4*)(hcur + row*HSTRIDE);
                    int c = tid & 15;
                    float4 z = make_float4(0.f, 0.f, 0.f, 0.f);
                    d[c] = z; d[c+16] = z; d[c+32] = z; d[c+48] = z;
                }
            }
            asm volatile("bar.sync 1, 128;" ::: "memory");

            // ---- recurrent matvecs (3 mats, 2 rows, 1 col), f32x2 packed
            const ulonglong2* W3 = (const ulonglong2*)(Ws + 3*MATS + col*WPAD);
            const ulonglong2* W4 = (const ulonglong2*)(Ws + 4*MATS + col*WPAD);
            const ulonglong2* W5 = (const ulonglong2*)(Ws + 5*MATS + col*WPAD);
            const ulonglong2* H0 = (const ulonglong2*)(hcur + r0*HSTRIDE);
            const ulonglong2* H1 = (const ulonglong2*)(hcur + r1*HSTRIDE);
            uint64_t a0=0,a1=0,a2=0,a3=0,a4=0,a5=0;
            #pragma unroll 4
            for (int k4 = 0; k4 < NH/4; k4++) {
                ulonglong2 w3 = W3[k4], w4 = W4[k4], w5 = W5[k4];
                ulonglong2 h0v = H0[k4], h1v = H1[k4];
                FMA2(a0, w3.x, h0v.x); FMA2(a0, w3.y, h0v.y);
                FMA2(a1, w4.x, h0v.x); FMA2(a1, w4.y, h0v.y);
                FMA2(a2, w5.x, h0v.x); FMA2(a2, w5.y, h0v.y);
                FMA2(a3, w3.x, h1v.x); FMA2(a3, w3.y, h1v.y);
                FMA2(a4, w4.x, h1v.x); FMA2(a4, w4.y, h1v.y);
                FMA2(a5, w5.x, h1v.x); FMA2(a5, w5.y, h1v.y);
            }

            // ---- gates (xg already includes input biases)
            const float* xgp = xg + p*(3*RPC*CPC);
            float xr0 = xgp[0*256 + r0*32 + col], xz0 = xgp[1*256 + r0*32 + col], xn0 = xgp[2*256 + r0*32 + col];
            float xr1 = xgp[0*256 + r1*32 + col], xz1 = xgp[1*256 + r1*32 + col], xn1 = xgp[2*256 + r1*32 + col];
            float hold0 = hcur[r0*HSTRIDE + jbase + col];
            float hold1 = hcur[r1*HSTRIDE + jbase + col];
            float rr0 = sigf(xr0 + pairsum(a0));
            float zz0 = sigf(xz0 + pairsum(a1));
            float nn0 = tanh_fast(xn0 + rr0*(pairsum(a2) + c_bhn));
            float hn0 = (1.0f - zz0)*nn0 + zz0*hold0;
            float rr1 = sigf(xr1 + pairsum(a3));
            float zz1 = sigf(xz1 + pairsum(a4));
            float nn1 = tanh_fast(xn1 + rr1*(pairsum(a5) + c_bhn));
            float hn1 = (1.0f - zz1)*nn1 + zz1*hold1;

            // ---- output
            float* ob = out + ((size_t)t*NR + rbase)*NH + jbase + col;
            ob[r0*NH] = hn0;
            ob[r1*NH] = hn1;

            // ---- stage + DSMEM broadcast to all 8 cluster CTAs' next buffer
            stg[r0*32 + col] = hn0;
            stg[r1*32 + col] = hn1;
            asm volatile("bar.sync 1, 128;" ::: "memory");
            {
                const uint32_t hn_off = hb_s + (uint32_t)((1-p)*(RPC*HSTRIDE))*4u;
                #pragma unroll
                for (int q = 0; q < 4; q++) {
                    int c   = tid + q*128;        // 0..511 over (rank, row, col4)
                    int rk  = c >> 6;
                    int f4  = c & 63;
                    int row = f4 >> 3;
                    int c4  = f4 & 7;
                    float4 v = *(const float4*)(stg + row*32 + c4*4);
                    uint32_t laddr = hn_off + (uint32_t)(row*HSTRIDE + jbase + c4*4)*4u;
                    uint32_t raddr;
                    asm("mapa.shared::cluster.u32 %0, %1, %2;" : "=r"(raddr) : "r"(laddr), "r"(rk));
                    asm volatile("st.shared::cluster.v4.f32 [%0], {%1,%2,%3,%4};"
                                 :: "r"(raddr), "f"(v.x), "f"(v.y), "f"(v.z), "f"(v.w) : "memory");
                }
            }
        } else {
            // ---- x-group: stage ins[t+1], project for step t+1, prefetch ins[t+2]
            int xt = tid - 128;
            {
                int f0 = xt*4;
                #pragma unroll
                for (int i = 0; i < 4; i++) {
                    int f4i = f0 + i;
                    int r = f4i >> 6, c4 = f4i & 63;
                    float4 v = (i==0)?px0:(i==1)?px1:(i==2)?px2:px3;
                    ((float4*)(xs + r*HSTRIDE))[c4] = v;
                }
            }
            asm volatile("bar.sync 2, 128;" ::: "memory");
            xproj(Ws, xs, xg + ((t+1)&1)*(3*RPC*CPC), col, r0, r1, c_bir, c_biz, c_bin);
            int tp = (t+2 < NT) ? (t+2) : (NT-1);
            const float4* s = (const float4*)ins + (size_t)(tp*NR + rbase)*64;
            px0 = s[xt*4+0]; px1 = s[xt*4+1]; px2 = s[xt*4+2]; px3 = s[xt*4+3];
        }

        CLUSTER_ARRIVE();   // release h pushes + xg writes; wait at top of t+1
    }
}

extern "C" void kernel_launch(void* const* d_in, const int* in_sizes, int n_in,
                              void* d_out, int out_size)
{
    const float* ins    = (const float*)d_in[0];
    const int*   resets = (const int*)d_in[1];     // jax bool -> int32 in harness
    const float* h0     = (const float*)d_in[2];
    const float* Wir    = (const float*)d_in[3];
    const float* Wiz    = (const float*)d_in[4];
    const float* Win    = (const float*)d_in[5];
    const float* bir    = (const float*)d_in[6];
    const float* biz    = (const float*)d_in[7];
    const float* bin    = (const float*)d_in[8];
    const float* Whr    = (const float*)d_in[9];
    const float* Whz    = (const float*)d_in[10];
    const float* Whn    = (const float*)d_in[11];
    const float* bhn    = (const float*)d_in[12];
    float* out = (float*)d_out;

    cudaFuncSetAttribute(gru_scan, cudaFuncAttributeMaxDynamicSharedMemorySize, SMEM_BYTES);
    gru_scan<<<NR, 256, SMEM_BYTES>>>(ins, resets, h0,
                                      Wir, Wiz, Win, bir, biz, bin,
                                      Whr, Whz, Whn, bhn, out);
}

// round 7
// speedup vs baseline: 1.1308x; 1.0315x over previous
#include <cuda_runtime.h>
#include <cstdint>
#include <cstddef>

// GRU scan, T=1024, rows=128, H=256. 16 clusters x 8 CTAs, 512 threads/CTA.
// warps 0-7  (h-group): recurrent matvecs + gates for step t  (serial path)
// warps 8-15 (x-group): input projections for step t+1
// Lane map per warp: 4 cols x 4 row-pairs x 2 k-halves; shfl.bfly(16) K-reduce.
// Weights: stride-256 XOR-swizzled slots (conflict-free). h/x rows: stride 260
// with 132-float k-half gap (conflict-free). Reset flags prefetched, applied as
// multiplicative masks (no smem zeroing, no extra barrier).

#define NT   1024
#define NR   128
#define NH   256
#define CSIZE 8
#define RPC  8
#define CPC  32
#define HSTRIDE 260        // h/x row stride (k-half 1 starts at +132)
#define HBUF (RPC*HSTRIDE) // 2080 floats per h buffer
#define WMAT 8192          // floats per weight matrix slice (32 cols x 256)

#define SMEM_FLOATS (6*WMAT + 2*HBUF + HBUF + 2*3*256 + 256 + 128)
#define SMEM_BYTES  (SMEM_FLOATS*4)   // 229248 B

#define FMA2(acc, a, b) asm("fma.rn.f32x2 %0, %1, %2, %0;" : "+l"(acc) : "l"(a), "l"(b))

__device__ __forceinline__ float tanh_fast(float x) {
    float y; asm("tanh.approx.f32 %0, %1;" : "=f"(y) : "f"(x)); return y;
}
__device__ __forceinline__ float sigf(float x) { return fmaf(0.5f, tanh_fast(0.5f*x), 0.5f); }
__device__ __forceinline__ float pairsum(uint64_t v) {
    return __uint_as_float((uint32_t)v) + __uint_as_float((uint32_t)(v >> 32));
}
__device__ __forceinline__ int kmap(int j) { return j + ((j >> 7) << 2); }  // pad map

#define CLUSTER_ARRIVE() asm volatile("barrier.cluster.arrive.aligned;" ::: "memory")
#define CLUSTER_WAIT()   asm volatile("barrier.cluster.wait.aligned;"   ::: "memory")

extern __shared__ float smem[];

// 3-matrix x 2-row half-K matvec. Returns 6 full sums (after shfl reduce).
__device__ __forceinline__ void matvec3(const float* Wbase,       // Ws + matGroup offset
                                        const float* vrows,      // hcur or xs
                                        int col, int kh, int c0, int r0, int r1,
                                        float* s /*[6]*/)
{
    const ulonglong2* W0 = (const ulonglong2*)(Wbase + 0*WMAT + (col*64 + kh*32)*4);
    const ulonglong2* W1 = (const ulonglong2*)(Wbase + 1*WMAT + (col*64 + kh*32)*4);
    const ulonglong2* W2 = (const ulonglong2*)(Wbase + 2*WMAT + (col*64 + kh*32)*4);
    const ulonglong2* V0 = (const ulonglong2*)(vrows + r0*HSTRIDE + kh*132);
    const ulonglong2* V1 = (const ulonglong2*)(vrows + r1*HSTRIDE + kh*132);
    uint64_t a0=0,a1=0,a2=0,a3=0,a4=0,a5=0;
    #pragma unroll 2
    for (int k4 = 0; k4 < 32; k4++) {
        int k4x = k4 ^ c0;                    // XOR-swizzled weight slot
        ulonglong2 w0 = W0[k4x], w1 = W1[k4x], w2 = W2[k4x];
        ulonglong2 v0 = V0[k4],  v1 = V1[k4];
        FMA2(a0, w0.x, v0.x); FMA2(a0, w0.y, v0.y);
        FMA2(a1, w1.x, v0.x); FMA2(a1, w1.y, v0.y);
        FMA2(a2, w2.x, v0.x); FMA2(a2, w2.y, v0.y);
        FMA2(a3, w0.x, v1.x); FMA2(a3, w0.y, v1.y);
        FMA2(a4, w1.x, v1.x); FMA2(a4, w1.y, v1.y);
        FMA2(a5, w2.x, v1.x); FMA2(a5, w2.y, v1.y);
    }
    s[0]=pairsum(a0); s[1]=pairsum(a1); s[2]=pairsum(a2);
    s[3]=pairsum(a3); s[4]=pairsum(a4); s[5]=pairsum(a5);
    #pragma unroll
    for (int i = 0; i < 6; i++) s[i] += __shfl_xor_sync(0xffffffffu, s[i], 16);
}

__global__ void __launch_bounds__(512, 1) __cluster_dims__(CSIZE, 1, 1)
gru_scan(const float* __restrict__ ins, const int* __restrict__ resets,
         const float* __restrict__ h0,
         const float* __restrict__ Wir, const float* __restrict__ Wiz, const float* __restrict__ Win,
         const float* __restrict__ bir, const float* __restrict__ biz, const float* __restrict__ bin,
         const float* __restrict__ Whr, const float* __restrict__ Whz, const float* __restrict__ Whn,
         const float* __restrict__ bhn,
         float* __restrict__ out)
{
    float* Ws  = smem;               // [6][WMAT]  XOR-swizzled weights
    float* hb  = Ws + 6*WMAT;        // [2][HBUF]  h double buffer
    float* xs  = hb + 2*HBUF;        // [HBUF]     staged ins slice
    float* xg  = xs + HBUF;          // [2][3][256] x-projection double buffer
    float* stg = xg + 2*3*256;       // [8][32]    new-h staging
    float* bsm = stg + 256;          // [4][32]    biases

    const int tid   = threadIdx.x;
    const int rank  = blockIdx.x & (CSIZE-1);
    const int rbase = (blockIdx.x / CSIZE) * RPC;
    const int jbase = rank * CPC;

    // ---- weights: gmem [k][j] -> smem swizzled [m][col][kh][k4x][k&3]
    {
        const float* srcs[6] = {Wir, Wiz, Win, Whr, Whz, Whn};
        int jj2 = tid & 31, ks = tid >> 5;           // 16 k-strides
        #pragma unroll
        for (int m = 0; m < 6; m++) {
            const float* Wm = srcs[m];
            for (int k0 = 0; k0 < NH; k0 += 16) {
                int k  = k0 + ks;
                float v = Wm[(size_t)k*NH + jbase + jj2];
                int k4 = (k >> 2) & 31, kh = k >> 7;
                int cc = ((kh << 2) ^ (jj2 & 3));
                int pos4 = jj2*64 + kh*32 + (k4 ^ cc);
                Ws[m*WMAT + pos4*4 + (k & 3)] = v;
            }
        }
    }
    if (tid < CPC) {
        bsm[tid]      = bir[jbase + tid];
        bsm[32 + tid] = biz[jbase + tid];
        bsm[64 + tid] = bin[jbase + tid];
        bsm[96 + tid] = bhn[jbase + tid];
    }
    // ---- h0 -> hb buf0 ; ins[0] -> xs  (512 float4, one per thread)
    {
        int r = tid >> 6, j = (tid & 63) * 4;
        int pos = r*HSTRIDE + kmap(j);
        *(float4*)(hb + pos) = ((const float4*)h0)[(size_t)rbase*64 + tid];
        *(float4*)(xs + pos) = ((const float4*)ins)[(size_t)rbase*64 + tid];
    }
    __syncthreads();

    // ---- lane mapping
    const bool is_h = (tid < 256);
    const int gtid = tid & 255;
    const int w    = gtid >> 5;
    const int lane = gtid & 31;
    const int colg = lane & 3, rowb = (lane >> 2) & 3, kh = lane >> 4;
    const int col  = w*4 + colg;
    const int r0   = rowb*2, r1 = r0 + 1;
    const int c0   = (kh << 2) ^ colg;
    const float c_bir = bsm[col], c_biz = bsm[32+col], c_bin = bsm[64+col], c_bhn = bsm[96+col];

    float4 px0, px1;          // x-group: 2 staged chunks for next step
    int   f0 = 0, f1 = 0;     // h-group: reset flags for current step
    if (!is_h) {
        float s[6];
        matvec3(Ws, xs, col, kh, c0, r0, r1, s);
        if (kh == 0) {
            float* g = xg;    // buf 0 (for t=0)
            g[0*256 + r0*32 + col] = s[0] + c_bir;
            g[1*256 + r0*32 + col] = s[1] + c_biz;
            g[2*256 + r0*32 + col] = s[2] + c_bin;
            g[0*256 + r1*32 + col] = s[3] + c_bir;
            g[1*256 + r1*32 + col] = s[4] + c_biz;
            g[2*256 + r1*32 + col] = s[5] + c_bin;
        }
        // prefetch ins[1] chunks
        int i0 = gtid, i1 = gtid + 256;
        px0 = ((const float4*)ins)[(size_t)(1*NR + rbase)*64 + i0];
        px1 = ((const float4*)ins)[(size_t)(1*NR + rbase)*64 + i1];
    } else {
        f0 = resets[rbase + r0];
        f1 = resets[rbase + r1];
    }
    CLUSTER_ARRIVE();   // releases weights/h0/xg0; pairs with wait at t=0

    const uint32_t hb_s = (uint32_t)__cvta_generic_to_shared(hb);

    for (int t = 0; t < NT; t++) {
        const int p = t & 1;
        float* hcur = hb + p*HBUF;

        CLUSTER_WAIT();   // acquire peers' h pushes + xg handoff

        if (is_h) {
            float m0 = f0 ? 0.0f : 1.0f;
            float m1 = f1 ? 0.0f : 1.0f;
            {   // prefetch next step's flags (off critical path)
                int tn = (t+1 < NT) ? (t+1) : (NT-1);
                f0 = resets[(size_t)tn*NR + rbase + r0];
                f1 = resets[(size_t)tn*NR + rbase + r1];
            }

            float s[6];
            matvec3(Ws + 3*WMAT, hcur, col, kh, c0, r0, r1, s);

            float hold0 = m0 * hcur[r0*HSTRIDE + kmap(jbase + col)];
            float hold1 = m1 * hcur[r1*HSTRIDE + kmap(jbase + col)];
            const float* xgp = xg + p*768;
            float xr0 = xgp[0*256 + r0*32 + col], xz0 = xgp[1*256 + r0*32 + col], xn0 = xgp[2*256 + r0*32 + col];
            float xr1 = xgp[0*256 + r1*32 + col], xz1 = xgp[1*256 + r1*32 + col], xn1 = xgp[2*256 + r1*32 + col];

            float rr0 = sigf(xr0 + m0*s[0]);
            float zz0 = sigf(xz0 + m0*s[1]);
            float nn0 = tanh_fast(xn0 + rr0*(m0*s[2] + c_bhn));
            float hn0 = (1.0f - zz0)*nn0 + zz0*hold0;
            float rr1 = sigf(xr1 + m1*s[3]);
            float zz1 = sigf(xz1 + m1*s[4]);
            float nn1 = tanh_fast(xn1 + rr1*(m1*s[5] + c_bhn));
            float hn1 = (1.0f - zz1)*nn1 + zz1*hold1;

            if (kh == 0) {
                stg[r0*32 + col] = hn0;
                stg[r1*32 + col] = hn1;
            }
            asm volatile("bar.sync 1, 256;" ::: "memory");

            // coalesced output: 64 threads write the full 8x32 slice as float4
            if (tid < 64) {
                int r = tid >> 3, c4 = tid & 7;
                float4 v = ((const float4*)stg)[r*8 + c4];
                *(float4*)(out + ((size_t)t*NR + rbase + r)*NH + jbase + c4*4) = v;
            }
            // DSMEM broadcast to all 8 cluster CTAs' next h buffer
            if (tid < 128) {
                const uint32_t hn_off = hb_s + (uint32_t)((1-p)*HBUF)*4u;
                #pragma unroll
                for (int q = 0; q < 4; q++) {
                    int c   = tid + q*128;            // (rank, row, col-chunk)
                    int rk  = c >> 6;
                    int f4  = c & 63;
                    int row = f4 >> 3;
                    int c4  = f4 & 7;
                    float4 v = ((const float4*)stg)[row*8 + c4];
                    int jfull = jbase + c4*4;
                    uint32_t laddr = hn_off + (uint32_t)(row*HSTRIDE + kmap(jfull))*4u;
                    uint32_t raddr;
                    asm("mapa.shared::cluster.u32 %0, %1, %2;" : "=r"(raddr) : "r"(laddr), "r"(rk));
                    asm volatile("st.shared::cluster.v4.f32 [%0], {%1,%2,%3,%4};"
                                 :: "r"(raddr), "f"(v.x), "f"(v.y), "f"(v.z), "f"(v.w) : "memory");
                }
            }
        } else {
            // ---- x-group: stage ins[t+1] into xs, project for step t+1
            {
                int i0 = gtid, i1 = gtid + 256;
                int ra = i0 >> 6, ja = (i0 & 63) * 4;
                int rb = i1 >> 6, jb = (i1 & 63) * 4;
                *(float4*)(xs + ra*HSTRIDE + kmap(ja)) = px0;
                *(float4*)(xs + rb*HSTRIDE + kmap(jb)) = px1;
            }
            asm volatile("bar.sync 2, 256;" ::: "memory");

            float s[6];
            matvec3(Ws, xs, col, kh, c0, r0, r1, s);
            if (kh == 0) {
                float* g = xg + (1-p)*768;
                g[0*256 + r0*32 + col] = s[0] + c_bir;
                g[1*256 + r0*32 + col] = s[1] + c_biz;
                g[2*256 + r0*32 + col] = s[2] + c_bin;
                g[0*256 + r1*32 + col] = s[3] + c_bir;
                g[1*256 + r1*32 + col] = s[4] + c_biz;
                g[2*256 + r1*32 + col] = s[5] + c_bin;
            }
            // prefetch ins[t+2] (clamped)
            int tp = (t+2 < NT) ? (t+2) : (NT-1);
            int i0 = gtid, i1 = gtid + 256;
            px0 = ((const float4*)ins)[(size_t)(tp*NR + rbase)*64 + i0];
            px1 = ((const float4*)ins)[(size_t)(tp*NR + rbase)*64 + i1];
        }

        CLUSTER_ARRIVE();   // release h pushes + xg writes; wait at top of t+1
    }
}

extern "C" void kernel_launch(void* const* d_in, const int* in_sizes, int n_in,
                              void* d_out, int out_size)
{
    const float* ins    = (const float*)d_in[0];
    const int*   resets = (const int*)d_in[1];     // jax bool -> int32 in harness
    const float* h0     = (const float*)d_in[2];
    const float* Wir    = (const float*)d_in[3];
    const float* Wiz    = (const float*)d_in[4];
    const float* Win    = (const float*)d_in[5];
    const float* bir    = (const float*)d_in[6];
    const float* biz    = (const float*)d_in[7];
    const float* bin    = (const float*)d_in[8];
    const float* Whr    = (const float*)d_in[9];
    const float* Whz    = (const float*)d_in[10];
    const float* Whn    = (const float*)d_in[11];
    const float* bhn    = (const float*)d_in[12];
    float* out = (float*)d_out;

    cudaFuncSetAttribute(gru_scan, cudaFuncAttributeMaxDynamicSharedMemorySize, SMEM_BYTES);
    gru_scan<<<NR, 512, SMEM_BYTES>>>(ins, resets, h0,
                                      Wir, Wiz, Win, bir, biz, bin,
                                      Whr, Whz, Whn, bhn, out);
}